// round 3
// baseline (speedup 1.0000x reference)
#include <cuda_runtime.h>
#include <math.h>

#define B_SZ  8
#define N_CTX 2048
#define D_IN  512
#define P_N   16
#define H_N   32
#define KF    (P_N * H_N)   // 512 fused (p,h) axis
#define NT    (N_CTX / 128)           // 16 tiles per dim
#define NTRI  (NT * (NT + 1) / 2)     // 136 upper-tri tiles

// Scratch (allocation-free rule: __device__ globals)
__device__ float g_F[(size_t)B_SZ * N_CTX * KF];   // 32 MB: F[b*N+n][p*H+h]
__device__ float g_max[B_SZ * N_CTX];
__device__ float g_inv[B_SZ * N_CTX];

// ---------------------------------------------------------------------------
// Shared 128x128x16 double-buffered fp32 GEMM core (NT: C = A * B^T).
// A: [*, lda] row-major, B: [*, ldb] row-major. 256 threads, 8x8 per thread.
// ---------------------------------------------------------------------------
struct GemmAcc { float a[8][8]; };

__device__ __forceinline__ void gemm_nt_128(const float* __restrict__ Ag,
                                            const float* __restrict__ Bg,
                                            int lda, int ldb, int Ktot,
                                            float (&As)[2][16][128],
                                            float (&Bs)[2][16][128],
                                            GemmAcc& C) {
    const int BK = 16;
    int tid  = threadIdx.x;
    int lrow = tid >> 2;            // 0..63
    int lk   = (tid & 3) * 4;       // 0,4,8,12
    int tx = tid & 15, ty = tid >> 4;

    // per-thread base pointers (hoisted; advance by BK each tile)
    const float* pa0 = Ag + (size_t)lrow * lda + lk;
    const float* pa1 = Ag + (size_t)(lrow + 64) * lda + lk;
    const float* pb0 = Bg + (size_t)lrow * ldb + lk;
    const float* pb1 = Bg + (size_t)(lrow + 64) * ldb + lk;

    float4 sa0, sa1, sb0, sb1;
    // prologue: stage k0 = 0
    sa0 = *(const float4*)(pa0);
    sa1 = *(const float4*)(pa1);
    sb0 = *(const float4*)(pb0);
    sb1 = *(const float4*)(pb1);
    As[0][lk + 0][lrow] = sa0.x; As[0][lk + 1][lrow] = sa0.y;
    As[0][lk + 2][lrow] = sa0.z; As[0][lk + 3][lrow] = sa0.w;
    As[0][lk + 0][lrow + 64] = sa1.x; As[0][lk + 1][lrow + 64] = sa1.y;
    As[0][lk + 2][lrow + 64] = sa1.z; As[0][lk + 3][lrow + 64] = sa1.w;
    Bs[0][lk + 0][lrow] = sb0.x; Bs[0][lk + 1][lrow] = sb0.y;
    Bs[0][lk + 2][lrow] = sb0.z; Bs[0][lk + 3][lrow] = sb0.w;
    Bs[0][lk + 0][lrow + 64] = sb1.x; Bs[0][lk + 1][lrow + 64] = sb1.y;
    Bs[0][lk + 2][lrow + 64] = sb1.z; Bs[0][lk + 3][lrow + 64] = sb1.w;
    __syncthreads();

    int buf = 0;
    for (int k0 = 0; k0 < Ktot; k0 += BK) {
        bool has_next = (k0 + BK) < Ktot;
        if (has_next) {   // issue next tile's loads before compute: LDG latency
            pa0 += BK; pa1 += BK; pb0 += BK; pb1 += BK;   // hides under FFMAs
            sa0 = *(const float4*)(pa0);
            sa1 = *(const float4*)(pa1);
            sb0 = *(const float4*)(pb0);
            sb1 = *(const float4*)(pb1);
        }
#pragma unroll
        for (int k = 0; k < BK; k++) {
            float ra[8], rb[8];
            *(float4*)(ra)     = *(const float4*)&As[buf][k][ty * 8];
            *(float4*)(ra + 4) = *(const float4*)&As[buf][k][ty * 8 + 4];
            *(float4*)(rb)     = *(const float4*)&Bs[buf][k][tx * 8];
            *(float4*)(rb + 4) = *(const float4*)&Bs[buf][k][tx * 8 + 4];
#pragma unroll
            for (int i = 0; i < 8; i++)
#pragma unroll
                for (int j = 0; j < 8; j++)
                    C.a[i][j] += ra[i] * rb[j];
        }
        if (has_next) {
            int nb = buf ^ 1;   // safe: all reads of nb completed before the
                                // barrier that ended the previous iteration
            As[nb][lk + 0][lrow] = sa0.x; As[nb][lk + 1][lrow] = sa0.y;
            As[nb][lk + 2][lrow] = sa0.z; As[nb][lk + 3][lrow] = sa0.w;
            As[nb][lk + 0][lrow + 64] = sa1.x; As[nb][lk + 1][lrow + 64] = sa1.y;
            As[nb][lk + 2][lrow + 64] = sa1.z; As[nb][lk + 3][lrow + 64] = sa1.w;
            Bs[nb][lk + 0][lrow] = sb0.x; Bs[nb][lk + 1][lrow] = sb0.y;
            Bs[nb][lk + 2][lrow] = sb0.z; Bs[nb][lk + 3][lrow] = sb0.w;
            Bs[nb][lk + 0][lrow + 64] = sb1.x; Bs[nb][lk + 1][lrow + 64] = sb1.y;
            Bs[nb][lk + 2][lrow + 64] = sb1.z; Bs[nb][lk + 3][lrow + 64] = sb1.w;
            __syncthreads();
            buf = nb;
        }
    }
}

// ---------------------------------------------------------------------------
// K1: F = relu(ctx @ W^T).  ctx: [16384,512], W: [512,512] (row = p*H+h).
// ---------------------------------------------------------------------------
__global__ __launch_bounds__(256, 2) void fc_kernel(const float* __restrict__ ctx,
                                                    const float* __restrict__ W) {
    __shared__ float As[2][16][128];
    __shared__ float Bs[2][16][128];
    int it = blockIdx.y, jt = blockIdx.x;
    GemmAcc C = {};
    gemm_nt_128(ctx + (size_t)it * 128 * D_IN, W + (size_t)jt * 128 * D_IN,
                D_IN, D_IN, D_IN, As, Bs, C);
    int tx = threadIdx.x & 15, ty = threadIdx.x >> 4;
    int row0 = it * 128 + ty * 8;
    int col0 = jt * 128 + tx * 8;
#pragma unroll
    for (int i = 0; i < 8; i++) {
        float4 o0 = make_float4(fmaxf(C.a[i][0], 0.f), fmaxf(C.a[i][1], 0.f),
                                fmaxf(C.a[i][2], 0.f), fmaxf(C.a[i][3], 0.f));
        float4 o1 = make_float4(fmaxf(C.a[i][4], 0.f), fmaxf(C.a[i][5], 0.f),
                                fmaxf(C.a[i][6], 0.f), fmaxf(C.a[i][7], 0.f));
        *(float4*)(&g_F[(size_t)(row0 + i) * KF + col0])     = o0;
        *(float4*)(&g_F[(size_t)(row0 + i) * KF + col0 + 4]) = o1;
    }
}

// ---------------------------------------------------------------------------
// K2: per batch, S = (F_b F_b^T)/P.  Compact triangular grid: linear tile id
// t in [0,136) decodes to upper-tri (it,jt). Mirror-store the transpose
// (bit-exact symmetry -> column softmax stats == row stats).
// ---------------------------------------------------------------------------
__global__ __launch_bounds__(256, 2) void syrk_kernel(float* __restrict__ S) {
    // decode linear upper-tri index: rows it=0..15, row it holds (16-it) tiles
    int t = blockIdx.x;
    int it = 0;
    {   // small loop, 16 iters max, uniform across block
        int rem = t;
        while (rem >= NT - it) { rem -= NT - it; it++; }
        t = rem;
    }
    int jt = it + t;
    int b = blockIdx.z;
    const float* Fb = g_F + (size_t)b * N_CTX * KF;
    float* Sb = S + (size_t)b * N_CTX * N_CTX;
    __shared__ float As[2][16][128];
    __shared__ float Bs[2][16][128];
    GemmAcc C = {};
    gemm_nt_128(Fb + (size_t)it * 128 * KF, Fb + (size_t)jt * 128 * KF,
                KF, KF, KF, As, Bs, C);
    const float s = 1.0f / (float)P_N;
    int tx = threadIdx.x & 15, ty = threadIdx.x >> 4;
    int row0 = it * 128 + ty * 8;
    int col0 = jt * 128 + tx * 8;
#pragma unroll
    for (int i = 0; i < 8; i++) {
        float4 o0 = make_float4(C.a[i][0] * s, C.a[i][1] * s, C.a[i][2] * s, C.a[i][3] * s);
        float4 o1 = make_float4(C.a[i][4] * s, C.a[i][5] * s, C.a[i][6] * s, C.a[i][7] * s);
        *(float4*)(&Sb[(size_t)(row0 + i) * N_CTX + col0])     = o0;
        *(float4*)(&Sb[(size_t)(row0 + i) * N_CTX + col0 + 4]) = o1;
    }
    if (it != jt) {
#pragma unroll
        for (int j = 0; j < 8; j++) {
            float4 m0 = make_float4(C.a[0][j] * s, C.a[1][j] * s, C.a[2][j] * s, C.a[3][j] * s);
            float4 m1 = make_float4(C.a[4][j] * s, C.a[5][j] * s, C.a[6][j] * s, C.a[7][j] * s);
            *(float4*)(&Sb[(size_t)(col0 + j) * N_CTX + row0])     = m0;
            *(float4*)(&Sb[(size_t)(col0 + j) * N_CTX + row0 + 4]) = m1;
        }
    }
}

// ---------------------------------------------------------------------------
// K3: per row r (== column r by symmetry): max and 1/sum(exp(.-max)).
// 2 rows per block (one per 4-warp half) to halve launch count.
// ---------------------------------------------------------------------------
__global__ __launch_bounds__(256) void stats_kernel(const float* __restrict__ S) {
    int half = threadIdx.x >> 7;                // 0 or 1
    int tid  = threadIdx.x & 127;               // lane within half
    int row  = blockIdx.x * 2 + half;           // 0 .. B*N-1
    const float4* r4 = (const float4*)(S + (size_t)row * N_CTX);
    float4 a = r4[tid];
    float4 b = r4[tid + 128];
    float4 c = r4[tid + 256];
    float4 d = r4[tid + 384];
    float m = fmaxf(fmaxf(fmaxf(fmaxf(a.x, a.y), fmaxf(a.z, a.w)),
                          fmaxf(fmaxf(b.x, b.y), fmaxf(b.z, b.w))),
                    fmaxf(fmaxf(fmaxf(c.x, c.y), fmaxf(c.z, c.w)),
                          fmaxf(fmaxf(d.x, d.y), fmaxf(d.z, d.w))));
    __shared__ float redm[2][4];
    __shared__ float reds[2][4];
#pragma unroll
    for (int o = 16; o > 0; o >>= 1) m = fmaxf(m, __shfl_xor_sync(0xffffffffu, m, o));
    if ((tid & 31) == 0) redm[half][tid >> 5] = m;
    __syncthreads();
    float bm = fmaxf(fmaxf(redm[half][0], redm[half][1]),
                     fmaxf(redm[half][2], redm[half][3]));

    float s = expf(a.x - bm) + expf(a.y - bm) + expf(a.z - bm) + expf(a.w - bm)
            + expf(b.x - bm) + expf(b.y - bm) + expf(b.z - bm) + expf(b.w - bm)
            + expf(c.x - bm) + expf(c.y - bm) + expf(c.z - bm) + expf(c.w - bm)
            + expf(d.x - bm) + expf(d.y - bm) + expf(d.z - bm) + expf(d.w - bm);
#pragma unroll
    for (int o = 16; o > 0; o >>= 1) s += __shfl_xor_sync(0xffffffffu, s, o);
    if ((tid & 31) == 0) reds[half][tid >> 5] = s;
    __syncthreads();
    if (tid == 0) {
        float t = reds[half][0] + reds[half][1] + reds[half][2] + reds[half][3];
        g_max[row] = bm;
        g_inv[row] = 1.0f / t;
    }
}

// ---------------------------------------------------------------------------
// K4: att[b,n,m] = exp(S[b,n,m]-max[b,m]) * inv[b,m] * mask[b,n] * mask[b,m]
// (softmax over axis n reads column-m stats == row-m stats by symmetry)
// ---------------------------------------------------------------------------
__global__ __launch_bounds__(256) void norm_kernel(float* __restrict__ S,
                                                   const int* __restrict__ mask) {
    const size_t total4 = (size_t)B_SZ * N_CTX * N_CTX / 4;
    size_t idx = (size_t)blockIdx.x * blockDim.x + threadIdx.x;
    size_t stride = (size_t)gridDim.x * blockDim.x;
    for (; idx < total4; idx += stride) {
        size_t m4 = idx & (N_CTX / 4 - 1);
        size_t n  = (idx >> 9) & (N_CTX - 1);
        size_t b  = idx >> 20;
        int m0 = (int)(m4 * 4);
        int base = (int)(b * N_CTX);
        float rn = (float)__ldg(&mask[base + (int)n]);
        float4 v = ((const float4*)S)[idx];
        int st = base + m0;
        v.x = expf(v.x - g_max[st + 0]) * g_inv[st + 0] * rn * (float)__ldg(&mask[base + m0 + 0]);
        v.y = expf(v.y - g_max[st + 1]) * g_inv[st + 1] * rn * (float)__ldg(&mask[base + m0 + 1]);
        v.z = expf(v.z - g_max[st + 2]) * g_inv[st + 2] * rn * (float)__ldg(&mask[base + m0 + 2]);
        v.w = expf(v.w - g_max[st + 3]) * g_inv[st + 3] * rn * (float)__ldg(&mask[base + m0 + 3]);
        ((float4*)S)[idx] = v;
    }
}

extern "C" void kernel_launch(void* const* d_in, const int* in_sizes, int n_in,
                              void* d_out, int out_size) {
    const float* ctx  = (const float*)d_in[0];   // [8,2048,512] f32
    const float* W    = (const float*)d_in[1];   // [16,32,512]  f32
    const int*   mask = (const int*)d_in[2];     // [8,2048]     i32
    float* S = (float*)d_out;                    // [8,2048,2048] f32

    fc_kernel<<<dim3(KF / 128, (B_SZ * N_CTX) / 128), 256>>>(ctx, W);
    syrk_kernel<<<dim3(NTRI, 1, B_SZ), 256>>>(S);
    stats_kernel<<<(B_SZ * N_CTX) / 2, 256>>>(S);
    norm_kernel<<<32768, 256>>>(S, mask);
}

// round 13
// speedup vs baseline: 3.6235x; 3.6235x over previous
#include <cuda_runtime.h>
#include <cuda_bf16.h>
#include <stdint.h>
#include <math.h>

#define B_SZ  8
#define N_CTX 2048
#define D_IN  512
#define P_N   16
#define KF    512
#define NT    (N_CTX / 128)
#define NTRI  (NT * (NT + 1) / 2)     // 136 upper-tri tiles

// ---------------- scratch (__device__ globals; no allocs allowed) ----------
__device__ __align__(16) __nv_bfloat16 g_ctxb[(size_t)B_SZ * N_CTX * D_IN];
__device__ __align__(16) __nv_bfloat16 g_Wb[KF * D_IN];
__device__ __align__(16) __nv_bfloat16 g_Fb[(size_t)B_SZ * N_CTX * KF];
__device__ float g_max[B_SZ * N_CTX];
__device__ float g_inv[B_SZ * N_CTX];

// ---------------- helpers (portable: sm_80+ features only) ------------------
__device__ __forceinline__ uint32_t smem_u32_of(const void* p) {
    uint32_t a;
    asm("{ .reg .u64 t; cvta.to.shared.u64 t, %1; cvt.u32.u64 %0, t; }"
        : "=r"(a) : "l"(p));
    return a;
}
#define SMEM_SWIZZLE_128B(o) ((o) ^ (((o) >> 3) & 0x70))

__device__ __forceinline__ void ldsm_x4(uint32_t* r, uint32_t addr) {
    asm volatile("ldmatrix.sync.aligned.m8n8.x4.shared.b16 {%0,%1,%2,%3}, [%4];"
        : "=r"(r[0]), "=r"(r[1]), "=r"(r[2]), "=r"(r[3]) : "r"(addr));
}
__device__ __forceinline__ void mma16816(float* c, const uint32_t* a, const uint32_t* b) {
    asm volatile(
        "mma.sync.aligned.m16n8k16.row.col.f32.bf16.bf16.f32 "
        "{%0,%1,%2,%3}, {%4,%5,%6,%7}, {%8,%9}, {%0,%1,%2,%3};"
        : "+f"(c[0]), "+f"(c[1]), "+f"(c[2]), "+f"(c[3])
        : "r"(a[0]), "r"(a[1]), "r"(a[2]), "r"(a[3]), "r"(b[0]), "r"(b[1]));
}
#define CP_ASYNC16(saddr, gaddr) \
    asm volatile("cp.async.cg.shared.global [%0], [%1], 16;" :: "r"(saddr), "l"(gaddr))
#define CP_COMMIT()  asm volatile("cp.async.commit_group;" ::: "memory")
#define CP_WAIT(n)   asm volatile("cp.async.wait_group %0;" :: "n"(n) : "memory")

// ---------------- shared-memory layout --------------------------------------
// A[2] 32KB | B[2] 32KB starting at 1024.  Mirror staging Dsm (128 x 129 f32)
// OVERLAPS A/B (dead after the final CP_WAIT(0) + compute + syncthreads).
#define SM_A      1024
#define SM_B0     (SM_A + 32768)
#define SM_D      SM_A
#define D_PITCH   129
#define SMEM_BYTES (SM_A + 128 * D_PITCH * 4)   // 67072 -> 2 CTAs/SM

struct Acc { float c[4][4][4]; };   // [m16 blk][n8 blk][frag reg]

// cp.async one 64-wide K chunk of A and B tiles into buffer (c&1)
__device__ __forceinline__ void issue_chunk(const __nv_bfloat16* __restrict__ Atile,
                                            const __nv_bfloat16* __restrict__ Btile,
                                            uint32_t su, int c, int tid) {
    const int buf = c & 1;
    const uint32_t ab = su + SM_A  + buf * 16384;
    const uint32_t bb = su + SM_B0 + buf * 16384;
#pragma unroll
    for (int q = 0; q < 4; ++q) {
        int idx = tid + q * 256;            // 0..1023 -> 16B segment
        int row = idx >> 3, seg = idx & 7;
        uint32_t so = SMEM_SWIZZLE_128B((uint32_t)(row * 128 + seg * 16));
        const __nv_bfloat16* ga = Atile + (size_t)row * KF + c * 64 + seg * 8;
        const __nv_bfloat16* gb = Btile + (size_t)row * KF + c * 64 + seg * 8;
        CP_ASYNC16(ab + so, ga);
        CP_ASYNC16(bb + so, gb);
    }
}

// C[128x128] += Atile[128x512] * Btile[128x512]^T  (both K-major bf16)
__device__ __forceinline__ void gemm_mainloop(const __nv_bfloat16* __restrict__ Atile,
                                              const __nv_bfloat16* __restrict__ Btile,
                                              uint32_t su, Acc& acc) {
    const int tid = threadIdx.x;
    const int lane = tid & 31, wid = tid >> 5;
    const int m_base = (wid >> 2) * 64;     // warp rows
    const int n_base = (wid & 3) * 32;      // warp cols

    issue_chunk(Atile, Btile, su, 0, tid);
    CP_COMMIT();
#pragma unroll 1
    for (int c = 0; c < 8; ++c) {
        if (c < 7) {
            issue_chunk(Atile, Btile, su, c + 1, tid);
            CP_COMMIT();
            CP_WAIT(1);                     // chunk c landed
        } else {
            CP_WAIT(0);
        }
        __syncthreads();
        const uint32_t ab = su + SM_A  + (c & 1) * 16384;
        const uint32_t bb = su + SM_B0 + (c & 1) * 16384;
        const uint32_t arow = (uint32_t)(lane & 15);
        const uint32_t asel = (uint32_t)((lane >> 4) << 4);        // +16B for k+8 half
        const uint32_t brow = (uint32_t)((lane & 7) + ((lane >> 4) << 3));
        const uint32_t bsel = (uint32_t)((((lane >> 3) & 1)) << 4);
#pragma unroll
        for (int ks = 0; ks < 4; ++ks) {
            const uint32_t kb = (uint32_t)(ks * 32);               // k0 bytes
            uint32_t af[4][4], bf[2][4];
#pragma unroll
            for (int mi = 0; mi < 4; ++mi) {
                uint32_t row = m_base + mi * 16 + arow;
                ldsm_x4(af[mi], ab + SMEM_SWIZZLE_128B(row * 128 + kb + asel));
            }
#pragma unroll
            for (int nb = 0; nb < 2; ++nb) {
                uint32_t row = n_base + nb * 16 + brow;
                ldsm_x4(bf[nb], bb + SMEM_SWIZZLE_128B(row * 128 + kb + bsel));
            }
#pragma unroll
            for (int mi = 0; mi < 4; ++mi)
#pragma unroll
                for (int nj = 0; nj < 4; ++nj)
                    mma16816(acc.c[mi][nj], af[mi], &bf[nj >> 1][(nj & 1) * 2]);
        }
        __syncthreads();
    }
}

// ---------------------------------------------------------------------------
// K0: fp32 -> bf16 convert (ctx then W)
// ---------------------------------------------------------------------------
#define CTX_V ((size_t)B_SZ * N_CTX * D_IN / 8)
#define W_V   ((size_t)KF * D_IN / 8)
__device__ __forceinline__ uint32_t pk2(float x, float y) {
    __nv_bfloat162 t = __floats2bfloat162_rn(x, y);
    return *reinterpret_cast<uint32_t*>(&t);
}
__global__ __launch_bounds__(256) void cvt_kernel(const float* __restrict__ ctx,
                                                  const float* __restrict__ W) {
    size_t i = (size_t)blockIdx.x * 256 + threadIdx.x;
    const float* s;
    __nv_bfloat16* d;
    if (i < CTX_V) { s = ctx + i * 8; d = g_ctxb + i * 8; }
    else           { size_t j = i - CTX_V; s = W + j * 8; d = g_Wb + j * 8; }
    float4 a = ((const float4*)s)[0];
    float4 b = ((const float4*)s)[1];
    uint4 o;
    o.x = pk2(a.x, a.y); o.y = pk2(a.z, a.w);
    o.z = pk2(b.x, b.y); o.w = pk2(b.z, b.w);
    *(uint4*)d = o;
}

// ---------------------------------------------------------------------------
// K1: F = relu(ctx_bf16 @ W_bf16^T) -> bf16.  grid (4, 128).
// ---------------------------------------------------------------------------
__global__ __launch_bounds__(256, 2) void fc_kernel() {
    extern __shared__ char smem[];
    uint32_t su = smem_u32_of(smem);
    const int it = blockIdx.y, jt = blockIdx.x;
    const int tid = threadIdx.x, lane = tid & 31, wid = tid >> 5;
    Acc acc = {};
    gemm_mainloop(g_ctxb + (size_t)it * 128 * KF, g_Wb + (size_t)jt * 128 * KF, su, acc);
    const int mw = it * 128 + (wid >> 2) * 64 + (lane >> 2);
    const int nw = jt * 128 + (wid & 3) * 32 + (lane & 3) * 2;
#pragma unroll
    for (int mi = 0; mi < 4; ++mi)
#pragma unroll
        for (int nj = 0; nj < 4; ++nj) {
            const float* c = acc.c[mi][nj];
            int r0 = mw + mi * 16, cc = nw + nj * 8;
            *(uint32_t*)&g_Fb[(size_t)r0 * KF + cc] =
                pk2(fmaxf(c[0], 0.f), fmaxf(c[1], 0.f));
            *(uint32_t*)&g_Fb[(size_t)(r0 + 8) * KF + cc] =
                pk2(fmaxf(c[2], 0.f), fmaxf(c[3], 0.f));
        }
}

// ---------------------------------------------------------------------------
// K2: S_b = (F_b F_b^T)/16, upper-tri tiles + mirrored stores.  grid (136,1,8)
// ---------------------------------------------------------------------------
__global__ __launch_bounds__(256, 2) void syrk_kernel(float* __restrict__ S) {
    extern __shared__ char smem[];
    uint32_t su = smem_u32_of(smem);
    int t = blockIdx.x, it = 0;
    { int rem = t; while (rem >= NT - it) { rem -= NT - it; it++; } t = rem; }
    const int jt = it + t;
    const int b = blockIdx.z;
    const int tid = threadIdx.x, lane = tid & 31, wid = tid >> 5;
    const __nv_bfloat16* Fb = g_Fb + (size_t)b * N_CTX * KF;
    float* Sb = S + (size_t)b * N_CTX * N_CTX;
    Acc acc = {};
    gemm_mainloop(Fb + (size_t)it * 128 * KF, Fb + (size_t)jt * 128 * KF, su, acc);

    const bool mirror = (it != jt);
    const int row0 = it * 128, col0 = jt * 128;
    const float s = 1.0f / (float)P_N;
    float* Dsm = (float*)(smem + SM_D);   // overlaps A/B: dead post-mainloop
    const int ml = (wid >> 2) * 64 + (lane >> 2);
    const int nl = (wid & 3) * 32 + (lane & 3) * 2;
#pragma unroll
    for (int mi = 0; mi < 4; ++mi)
#pragma unroll
        for (int nj = 0; nj < 4; ++nj) {
            const float* c = acc.c[mi][nj];
            int rl = ml + mi * 16, cl = nl + nj * 8;
            float v0 = c[0] * s, v1 = c[1] * s, v2 = c[2] * s, v3 = c[3] * s;
            *(float2*)&Sb[(size_t)(row0 + rl) * N_CTX + col0 + cl] = make_float2(v0, v1);
            *(float2*)&Sb[(size_t)(row0 + rl + 8) * N_CTX + col0 + cl] = make_float2(v2, v3);
            if (mirror) {
                Dsm[rl * D_PITCH + cl] = v0;       Dsm[rl * D_PITCH + cl + 1] = v1;
                Dsm[(rl + 8) * D_PITCH + cl] = v2; Dsm[(rl + 8) * D_PITCH + cl + 1] = v3;
            }
        }
    __syncthreads();
    if (mirror) {
        // transposed coalesced stores: lanes sweep r, fixed output row c
        for (int idx = tid; idx < 4096; idx += 256) {
            int c = idx >> 5, r4 = idx & 31;
            float4 v = make_float4(Dsm[(r4 * 4 + 0) * D_PITCH + c],
                                   Dsm[(r4 * 4 + 1) * D_PITCH + c],
                                   Dsm[(r4 * 4 + 2) * D_PITCH + c],
                                   Dsm[(r4 * 4 + 3) * D_PITCH + c]);
            *(float4*)(Sb + (size_t)(col0 + c) * N_CTX + row0 + r4 * 4) = v;
        }
    }
}

// ---------------------------------------------------------------------------
// K3: per row r (== column r by symmetry): max and 1/sum(exp(.-max)).
// ---------------------------------------------------------------------------
__global__ __launch_bounds__(256) void stats_kernel(const float* __restrict__ S) {
    int half = threadIdx.x >> 7;
    int tid  = threadIdx.x & 127;
    int row  = blockIdx.x * 2 + half;
    const float4* r4 = (const float4*)(S + (size_t)row * N_CTX);
    float4 a = r4[tid];
    float4 b = r4[tid + 128];
    float4 c = r4[tid + 256];
    float4 d = r4[tid + 384];
    float m = fmaxf(fmaxf(fmaxf(fmaxf(a.x, a.y), fmaxf(a.z, a.w)),
                          fmaxf(fmaxf(b.x, b.y), fmaxf(b.z, b.w))),
                    fmaxf(fmaxf(fmaxf(c.x, c.y), fmaxf(c.z, c.w)),
                          fmaxf(fmaxf(d.x, d.y), fmaxf(d.z, d.w))));
    __shared__ float redm[2][4];
    __shared__ float reds[2][4];
#pragma unroll
    for (int o = 16; o > 0; o >>= 1) m = fmaxf(m, __shfl_xor_sync(0xffffffffu, m, o));
    if ((tid & 31) == 0) redm[half][tid >> 5] = m;
    __syncthreads();
    float bm = fmaxf(fmaxf(redm[half][0], redm[half][1]),
                     fmaxf(redm[half][2], redm[half][3]));
    float s = __expf(a.x - bm) + __expf(a.y - bm) + __expf(a.z - bm) + __expf(a.w - bm)
            + __expf(b.x - bm) + __expf(b.y - bm) + __expf(b.z - bm) + __expf(b.w - bm)
            + __expf(c.x - bm) + __expf(c.y - bm) + __expf(c.z - bm) + __expf(c.w - bm)
            + __expf(d.x - bm) + __expf(d.y - bm) + __expf(d.z - bm) + __expf(d.w - bm);
#pragma unroll
    for (int o = 16; o > 0; o >>= 1) s += __shfl_xor_sync(0xffffffffu, s, o);
    if ((tid & 31) == 0) reds[half][tid >> 5] = s;
    __syncthreads();
    if (tid == 0) {
        g_max[row] = bm;
        g_inv[row] = 1.0f / (reds[half][0] + reds[half][1] + reds[half][2] + reds[half][3]);
    }
}

// ---------------------------------------------------------------------------
// K4: att[b,n,m] = exp(S-max[b,m]) * inv[b,m] * mask[b,n] * mask[b,m]
// grid (mchunk=4, nseg=8, b=8). Per-thread m-quad stats hoisted to registers.
// ---------------------------------------------------------------------------
__global__ __launch_bounds__(256) void norm_kernel(float* __restrict__ S,
                                                   const int* __restrict__ mask) {
    __shared__ float4 s_max4[128];
    __shared__ float4 s_fm4[128];
    __shared__ float  s_rmask[256];
    const int b = blockIdx.z, mc = blockIdx.x, ns = blockIdx.y;
    const int base = b * N_CTX;
    const int m0 = mc * 512;
    const int tid = threadIdx.x;
    if (tid < 128) {
        int m = m0 + tid * 4;
        float4 mx = *(const float4*)&g_max[base + m];
        float4 iv = *(const float4*)&g_inv[base + m];
        float4 fm;
        fm.x = iv.x * (float)__ldg(&mask[base + m + 0]);
        fm.y = iv.y * (float)__ldg(&mask[base + m + 1]);
        fm.z = iv.z * (float)__ldg(&mask[base + m + 2]);
        fm.w = iv.w * (float)__ldg(&mask[base + m + 3]);
        s_max4[tid] = mx;
        s_fm4[tid]  = fm;
    }
    s_rmask[tid] = (float)__ldg(&mask[base + ns * 256 + tid]);
    __syncthreads();
    const int half = tid >> 7, q = tid & 127;
    const float4 mx = s_max4[q];
    const float4 fm = s_fm4[q];
#pragma unroll 4
    for (int i = 0; i < 256; i += 2) {
        int n = ns * 256 + i + half;
        float rn = s_rmask[i + half];
        float4* p = (float4*)(S + ((size_t)base + n) * N_CTX + m0) + q;
        float4 v = *p;
        v.x = __expf(v.x - mx.x) * fm.x * rn;
        v.y = __expf(v.y - mx.y) * fm.y * rn;
        v.z = __expf(v.z - mx.z) * fm.z * rn;
        v.w = __expf(v.w - mx.w) * fm.w * rn;
        *p = v;
    }
}

extern "C" void kernel_launch(void* const* d_in, const int* in_sizes, int n_in,
                              void* d_out, int out_size) {
    const float* ctx  = (const float*)d_in[0];   // [8,2048,512] f32
    const float* W    = (const float*)d_in[1];   // [16,32,512]  f32
    const int*   mask = (const int*)d_in[2];     // [8,2048]     i32
    float* S = (float*)d_out;                    // [8,2048,2048] f32

    cudaFuncSetAttribute(fc_kernel, cudaFuncAttributeMaxDynamicSharedMemorySize, SMEM_BYTES);
    cudaFuncSetAttribute(syrk_kernel, cudaFuncAttributeMaxDynamicSharedMemorySize, SMEM_BYTES);

    cvt_kernel<<<(unsigned)((CTX_V + W_V) / 256), 256>>>(ctx, W);
    fc_kernel<<<dim3(KF / 128, (B_SZ * N_CTX) / 128), 256, SMEM_BYTES>>>();
    syrk_kernel<<<dim3(NTRI, 1, B_SZ), 256, SMEM_BYTES>>>(S);
    stats_kernel<<<(B_SZ * N_CTX) / 2, 256>>>(S);
    norm_kernel<<<dim3(4, 8, B_SZ), 256>>>(S, mask);
}